// round 14
// baseline (speedup 1.0000x reference)
#include <cuda_runtime.h>
#include <cstdint>

// DocREDModel: entity-pool -> tanh-projection -> block-bilinear classifier
// B=16 S=2048 H=768 E=32 M=4 P=128 L=97 BLOCK=64
//
// Factorized pipeline:
//   C[e2, k1, l]  = sum_j zt[e2, cb*64+j] * Wc[k1*64+j, l]       (4.8 GF)
//   C96[e2, k1]   = sum_j zt[e2, cb*64+j] * w96[k1*64+j]
//   Dp[z][b,e1,e2,l] = partial over k-quarter z of zh @ C        (2.4 GF)
//   D96[b,e1,e2]  = zh . C96
//   out[n, l]     = (l<96 ? sum_z Dp[z][...] : D96[...]) + bc[l]
// stage1 v5: thread tile 8e2 x 4l (16 acc ull), 3 LDS wavefronts / 32 FMA-cyc.

#define B_    16
#define S_    2048
#define H_    768
#define E_    32
#define L_    97
#define CH    96
#define NROWS 2048
#define NENT  512
#define KTOT  49152
#define DPBLK (B_ * E_ * E_ * CH)

typedef unsigned long long ull;

__device__ float g_ent[NENT * H_];
__device__ float g_zh[NENT * H_];
__device__ float g_zt[NENT * H_];
__device__ float g_w96[KTOT];
__device__ float g_C[(size_t)NENT * H_ * CH];      // 151 MB scratch
__device__ float g_C96[NENT * H_];
__device__ float g_Dp[4 * DPBLK];                  // 25 MB partials
__device__ float g_D96[B_ * E_ * E_];

__device__ __forceinline__ ull ffma2(ull a, ull b, ull c) {
    ull d; asm("fma.rn.f32x2 %0, %1, %2, %3;" : "=l"(d) : "l"(a), "l"(b), "l"(c));
    return d;
}
__device__ __forceinline__ ull fsplat(float x) {
    ull d; asm("mov.b64 %0, {%1, %1};" : "=l"(d) : "f"(x));
    return d;
}
__device__ __forceinline__ float lo32(ull v) { return __uint_as_float((unsigned)(v & 0xffffffffull)); }
__device__ __forceinline__ float hi32(ull v) { return __uint_as_float((unsigned)(v >> 32)); }
__device__ __forceinline__ void cp16(uint32_t dst, const void* src) {
    asm volatile("cp.async.cg.shared.global [%0], [%1], 16;" :: "r"(dst), "l"(src));
}

// ---------------------------------------------------------------- kernel 1
__global__ void build_ent_kernel(const float* __restrict__ feats,
                                 const int* __restrict__ pos) {
    int be = blockIdx.x;
    int b  = be >> 5;
    const int* pp = pos + be * 4;
    int p0 = pp[0], p1 = pp[1], p2 = pp[2], p3 = pp[3];
    float w1 = (p1 != p0) ? 1.f : 0.f;
    float w2 = (p2 != p0 && p2 != p1) ? 1.f : 0.f;
    float w3 = (p3 != p0 && p3 != p1 && p3 != p2) ? 1.f : 0.f;
    const float* base = feats + (size_t)b * S_ * H_;
    const float4* r0 = (const float4*)(base + (size_t)p0 * H_);
    const float4* r1 = (const float4*)(base + (size_t)p1 * H_);
    const float4* r2 = (const float4*)(base + (size_t)p2 * H_);
    const float4* r3 = (const float4*)(base + (size_t)p3 * H_);
    int t = threadIdx.x;   // 192 threads * float4 = 768
    float4 v0 = r0[t], v1 = r1[t], v2 = r2[t], v3 = r3[t];
    float4 o;
    o.x = v0.x + w1 * v1.x + w2 * v2.x + w3 * v3.x;
    o.y = v0.y + w1 * v1.y + w2 * v2.y + w3 * v3.y;
    o.z = v0.z + w1 * v1.z + w2 * v2.z + w3 * v3.z;
    o.w = v0.w + w1 * v1.w + w2 * v2.w + w3 * v3.w;
    ((float4*)(g_ent + (size_t)be * H_))[t] = o;
}

// ---------------------------------------------------------------- kernel 2
__global__ void __launch_bounds__(256)
gemm_tanh_kernel(const float* __restrict__ Wh, const float* __restrict__ bh,
                 const float* __restrict__ Wt, const float* __restrict__ bt) {
    const float* W    = blockIdx.z ? Wt : Wh;
    const float* bias = blockIdx.z ? bt : bh;
    float*       Z    = blockIdx.z ? g_zt : g_zh;

    __shared__ float AsT[16 * 68];
    __shared__ float Bd[16 * 256];

    int tid = threadIdx.x;
    int mg  = tid & 15;
    int ng  = tid >> 4;
    int m0  = blockIdx.x * 64;
    int n0  = blockIdx.y * 128;

    ull acc[2][8];
#pragma unroll
    for (int p = 0; p < 2; p++)
#pragma unroll
        for (int c = 0; c < 8; c++) acc[p][c] = 0ull;

    for (int k0 = 0; k0 < H_; k0 += 16) {
        __syncthreads();
#pragma unroll
        for (int e = tid; e < 1024; e += 256) {
            int kk = e & 15, m = e >> 4;
            AsT[kk * 68 + m] = g_ent[(m0 + m) * H_ + k0 + kk];
        }
#pragma unroll
        for (int e = tid; e < 2048; e += 256) {
            int n = e & 127, kk = e >> 7;
            float w = W[(k0 + kk) * H_ + n0 + n];
            ((float2*)Bd)[kk * 128 + n] = make_float2(w, w);
        }
        __syncthreads();
#pragma unroll
        for (int kk = 0; kk < 16; kk++) {
            ulonglong2 av = *(const ulonglong2*)&AsT[kk * 68 + mg * 4];
            const ulonglong2* wp = (const ulonglong2*)&Bd[kk * 256 + ng * 16];
            ulonglong2 w01 = wp[0], w23 = wp[1], w45 = wp[2], w67 = wp[3];
            ull w[8] = {w01.x, w01.y, w23.x, w23.y, w45.x, w45.y, w67.x, w67.y};
#pragma unroll
            for (int c = 0; c < 8; c++) {
                acc[0][c] = ffma2(av.x, w[c], acc[0][c]);
                acc[1][c] = ffma2(av.y, w[c], acc[1][c]);
            }
        }
    }
#pragma unroll
    for (int p = 0; p < 2; p++) {
#pragma unroll
        for (int c = 0; c < 8; c++) {
            int n = n0 + ng * 8 + c;
            float bv = bias[n];
            int m = m0 + mg * 4 + 2 * p;
            Z[m * H_ + n]       = tanhf(lo32(acc[p][c]) + bv);
            Z[(m + 1) * H_ + n] = tanhf(hi32(acc[p][c]) + bv);
        }
    }
}

// ---------------------------------------------------------------- w96 extract
__global__ void w96_extract_kernel(const float* __restrict__ Wc) {
    int k = blockIdx.x * blockDim.x + threadIdx.x;
    if (k < KTOT) g_w96[k] = Wc[(size_t)k * L_ + 96];
}

// ---------------------------------------------------------------- stage 1 v5
// C[e2, k1, l] = sum_j zt[e2, cb*64+j] * Wc[k1*64+j, l],  k1 = cb*64 + iz.
// Grid (12 cb, 8 e2-tiles of 64, 64 iz), 192 threads.
// Thread tile 8 e2 x 4 l: 16 acc ull (~32 regs), per warp-k only 3 LDS
// wavefronts vs 32 FMA-cycles.  smem 42KB -> 4-5 CTA/SM.
__global__ void __launch_bounds__(192)
stage1_kernel(const float* __restrict__ Wc) {
    __shared__ float As[64 * 68];      // [j][e2], stride 68  (17.4KB)
    __shared__ float Bs[64 * 96];      // [j][l]              (24.6KB)

    int tid = threadIdx.x;
    int cb  = blockIdx.x;
    int e0  = blockIdx.y * 64;
    int k1  = cb * 64 + blockIdx.z;

    for (int e = tid; e < 4096; e += 192) {
        int j = e & 63, m = e >> 6;
        As[j * 68 + m] = g_zt[(e0 + m) * H_ + cb * 64 + j];
    }
    {
        const float* wrow = Wc + (size_t)(k1 * 64) * L_;
        for (int e = tid; e < 6144; e += 192) {
            int j = e / 96, l = e - j * 96;
            Bs[j * 96 + l] = wrow[(size_t)j * L_ + l];
        }
    }
    __syncthreads();

    int mg = tid % 8;                  // 8 e2 rows (consecutive 8 floats)
    int lg = tid / 8;                  // 24 l-groups of 4
    int l0 = lg * 4;
    const float* aptr = As + mg * 8;
    const float* bptr = Bs + l0;

    ull acc[8][2];
#pragma unroll
    for (int m = 0; m < 8; m++) {
        acc[m][0] = 0ull;
        acc[m][1] = 0ull;
    }

#pragma unroll 4
    for (int k = 0; k < 64; k++) {
        float4 x0 = *(const float4*)(aptr + k * 68);
        float4 x1 = *(const float4*)(aptr + k * 68 + 4);
        ulonglong2 bq = *(const ulonglong2*)(bptr + k * 96);   // 4 l = 2 pairs
        float av[8] = {x0.x, x0.y, x0.z, x0.w, x1.x, x1.y, x1.z, x1.w};
#pragma unroll
        for (int m = 0; m < 8; m++) {
            ull s = fsplat(av[m]);
            acc[m][0] = ffma2(s, bq.x, acc[m][0]);
            acc[m][1] = ffma2(s, bq.y, acc[m][1]);
        }
    }

#pragma unroll
    for (int m = 0; m < 8; m++) {
        float* cptr = g_C + ((size_t)(e0 + mg * 8 + m) * H_ + k1) * CH + l0;
        *(ulonglong2*)cptr = make_ulonglong2(acc[m][0], acc[m][1]);
    }
}

// ---------------------------------------------------------------- c96
__global__ void __launch_bounds__(256)
c96_kernel() {
    __shared__ float zts[64 * 68];
    __shared__ float wts[64 * 64];

    int tid = threadIdx.x;
    int cb  = blockIdx.x;
    int e0  = blockIdx.y * 64;

    for (int e = tid; e < 4096; e += 256) {
        int j = e & 63, m = e >> 6;
        zts[j * 68 + m] = g_zt[(e0 + m) * H_ + cb * 64 + j];
    }
    for (int e = tid; e < 1024; e += 256)
        ((float4*)wts)[e] = ((const float4*)(g_w96 + cb * 4096))[e];
    __syncthreads();

    int mg = tid & 15;
    int i0 = (tid >> 4) * 4;

    ull acc[2][4];
#pragma unroll
    for (int p = 0; p < 2; p++)
#pragma unroll
        for (int i = 0; i < 4; i++) acc[p][i] = 0ull;

#pragma unroll 4
    for (int j = 0; j < 64; j++) {
        ulonglong2 a = *(const ulonglong2*)&zts[j * 68 + mg * 4];
#pragma unroll
        for (int i = 0; i < 4; i++) {
            ull w = fsplat(wts[(i0 + i) * 64 + j]);
            acc[0][i] = ffma2(a.x, w, acc[0][i]);
            acc[1][i] = ffma2(a.y, w, acc[1][i]);
        }
    }

#pragma unroll
    for (int p = 0; p < 2; p++) {
        int e2a = e0 + mg * 4 + 2 * p;
#pragma unroll
        for (int i = 0; i < 4; i++) {
            int k1 = cb * 64 + i0 + i;
            g_C96[e2a * H_ + k1]       = lo32(acc[p][i]);
            g_C96[(e2a + 1) * H_ + k1] = hi32(acc[p][i]);
        }
    }
}

// ---------------------------------------------------------------- stage 2
// Dp[z][b,e1,e2,l] = sum_{k in quarter z} zh[b*32+e1,k] * C[b*32+e2,k,l]
// Grid (16 b, 32 e2, 4 z), 256 threads; 3 chunks of 64 k per CTA.
#define S2_AS_F (64 * 36)
#define S2_BS_F (64 * 96)
#define S2_SMEM ((S2_AS_F + 2 * S2_BS_F) * 4)
__global__ void __launch_bounds__(256)
stage2_kernel() {
    extern __shared__ float s2[];
    float* As = s2;                    // [kk][e1], stride 36
    float* Bs = s2 + S2_AS_F;          // [2][kk][96]

    int tid = threadIdx.x;
    int b   = blockIdx.x;
    int e2  = blockIdx.y;
    int z   = blockIdx.z;
    const float* crow = g_C + (size_t)(b * E_ + e2) * H_ * CH + (size_t)(z * 192) * CH;
    const float* zrow = g_zh + (size_t)(b * E_) * H_ + z * 192;
    uint32_t bs_u = (uint32_t)__cvta_generic_to_shared(Bs);

    int mg = tid >> 4;
    int ng = tid & 15;
    int l0 = ng * 6;

    float pa[8];
#pragma unroll
    for (int s = 0; s < 8; s++) {
        int e = tid + s * 256, e1 = e >> 6, kk = e & 63;
        pa[s] = zrow[e1 * H_ + kk];
    }
#pragma unroll
    for (int s = 0; s < 6; s++) {
        int u = tid + s * 256;
        int k = u / 24, c = u - k * 24;
        cp16(bs_u + (unsigned)(k * 96 + c * 4) * 4, crow + (size_t)k * CH + c * 4);
    }
    asm volatile("cp.async.commit_group;");

    ull acc[2][3];
#pragma unroll
    for (int m = 0; m < 2; m++)
#pragma unroll
        for (int p = 0; p < 3; p++) acc[m][p] = 0ull;

    for (int kc = 0; kc < 3; kc++) {
        int buf = kc & 1;
        asm volatile("cp.async.wait_group 0;");
        __syncthreads();
#pragma unroll
        for (int s = 0; s < 8; s++) {
            int e = tid + s * 256, e1 = e >> 6, kk = e & 63;
            As[kk * 36 + e1] = pa[s];
        }
        if (kc < 2) {
            const float* cc = crow + (size_t)(kc + 1) * 64 * CH;
            uint32_t db = bs_u + (unsigned)((buf ^ 1) * S2_BS_F) * 4;
#pragma unroll
            for (int s = 0; s < 6; s++) {
                int u = tid + s * 256;
                int k = u / 24, c = u - k * 24;
                cp16(db + (unsigned)(k * 96 + c * 4) * 4, cc + (size_t)k * CH + c * 4);
            }
            asm volatile("cp.async.commit_group;");
        }
        __syncthreads();
        if (kc < 2) {
            const float* zc = zrow + (kc + 1) * 64;
#pragma unroll
            for (int s = 0; s < 8; s++) {
                int e = tid + s * 256, e1 = e >> 6, kk = e & 63;
                pa[s] = zc[e1 * H_ + kk];
            }
        }

        const float* bb = Bs + buf * S2_BS_F + l0;
#pragma unroll 4
        for (int k = 0; k < 64; k++) {
            ull a = *(const ull*)&As[k * 36 + mg * 2];
            ull s0 = fsplat(lo32(a));
            ull s1 = fsplat(hi32(a));
            ull b0 = *(const ull*)(bb + k * 96);
            ull b1 = *(const ull*)(bb + k * 96 + 2);
            ull b2 = *(const ull*)(bb + k * 96 + 4);
            acc[0][0] = ffma2(s0, b0, acc[0][0]);
            acc[1][0] = ffma2(s1, b0, acc[1][0]);
            acc[0][1] = ffma2(s0, b1, acc[0][1]);
            acc[1][1] = ffma2(s1, b1, acc[1][1]);
            acc[0][2] = ffma2(s0, b2, acc[0][2]);
            acc[1][2] = ffma2(s1, b2, acc[1][2]);
        }
    }

#pragma unroll
    for (int m = 0; m < 2; m++) {
        int e1 = mg * 2 + m;
        float* dptr = g_Dp + (size_t)z * DPBLK +
                      (size_t)((b * E_ + e1) * E_ + e2) * CH + l0;
        *(ull*)(dptr + 0) = acc[m][0];
        *(ull*)(dptr + 2) = acc[m][1];
        *(ull*)(dptr + 4) = acc[m][2];
    }
}

// ---------------------------------------------------------------- d96
__global__ void __launch_bounds__(128)
d96_kernel() {
    __shared__ float c96s[H_];
    int b  = blockIdx.x;
    int e2 = blockIdx.y;
    int tid = threadIdx.x;
    const float* crow = g_C96 + (size_t)(b * E_ + e2) * H_;
    for (int s = tid; s < H_ / 4; s += 128)
        ((float4*)c96s)[s] = ((const float4*)crow)[s];
    __syncthreads();

    int e1 = tid >> 2, q = tid & 3;
    const float* zr = g_zh + (size_t)(b * E_ + e1) * H_;
    float acc = 0.f;
#pragma unroll 8
    for (int k = q; k < H_; k += 4) acc += zr[k] * c96s[k];
    acc += __shfl_down_sync(0xffffffffu, acc, 2, 4);
    acc += __shfl_down_sync(0xffffffffu, acc, 1, 4);
    if (q == 0) g_D96[(b * E_ + e1) * E_ + e2] = acc;
}

// ---------------------------------------------------------------- gather
__global__ void gather_kernel(const int* __restrict__ ht,
                              const float* __restrict__ bc,
                              float* __restrict__ out) {
    int idx = blockIdx.x * 256 + threadIdx.x;
    if (idx >= NROWS * L_) return;
    int n = idx / L_, l = idx - n * L_;
    int b  = n >> 7;
    int e1 = ht[2 * n];
    int e2 = ht[2 * n + 1];
    size_t pe = (size_t)((b * E_ + e1) * E_ + e2);
    float v;
    if (l < CH) {
        v = g_Dp[pe * CH + l] + g_Dp[DPBLK + pe * CH + l] +
            g_Dp[2 * DPBLK + pe * CH + l] + g_Dp[3 * DPBLK + pe * CH + l];
    } else {
        v = g_D96[pe];
    }
    out[idx] = v + bc[l];
}

// ---------------------------------------------------------------- launch
extern "C" void kernel_launch(void* const* d_in, const int* in_sizes, int n_in,
                              void* d_out, int out_size) {
    const float* feats = (const float*)d_in[0];
    const int*   pos   = (const int*)d_in[1];
    const int*   ht    = (const int*)d_in[2];
    const float* Wh    = (const float*)d_in[3];
    const float* bh    = (const float*)d_in[4];
    const float* Wt    = (const float*)d_in[5];
    const float* bt    = (const float*)d_in[6];
    const float* Wc    = (const float*)d_in[7];
    const float* bc    = (const float*)d_in[8];
    float*       out   = (float*)d_out;

    cudaFuncSetAttribute(stage2_kernel,
                         cudaFuncAttributeMaxDynamicSharedMemorySize, S2_SMEM);

    build_ent_kernel<<<NENT, 192>>>(feats, pos);                  // 1

    dim3 g2(NENT / 64, H_ / 128, 2);
    gemm_tanh_kernel<<<g2, 256>>>(Wh, bh, Wt, bt);                // 2

    w96_extract_kernel<<<(KTOT + 255) / 256, 256>>>(Wc);          // 3

    dim3 g5(12, 8, 64);
    stage1_kernel<<<g5, 192>>>(Wc);                               // 4 (ncu)

    dim3 gc(12, 8);
    c96_kernel<<<gc, 256>>>();                                    // 5

    dim3 g6(B_, E_, 4);
    stage2_kernel<<<g6, 256, S2_SMEM>>>();                        // 6

    dim3 gd(B_, E_);
    d96_kernel<<<gd, 128>>>();                                    // 7

    gather_kernel<<<(NROWS * L_ + 255) / 256, 256>>>(ht, bc, out); // 8
}

// round 15
// speedup vs baseline: 1.1778x; 1.1778x over previous
#include <cuda_runtime.h>
#include <cstdint>

// DocREDModel: entity-pool -> tanh-projection -> block-bilinear classifier
// B=16 S=2048 H=768 E=32 M=4 P=128 L=97 BLOCK=64
//
// Factorized pipeline:
//   C[e2, k1, l]  = sum_j zt[e2, cb*64+j] * Wc[k1*64+j, l]       (4.8 GF)
//   C96[e2, k1]   = sum_j zt[e2, cb*64+j] * w96[k1*64+j]
//   Dp[z][b,e1,e2,l] = partial over k-quarter z of zh @ C        (2.4 GF)
//   D96[b,e1,e2]  = zh . C96
//   out[n, l]     = (l<96 ? sum_z Dp[z][...] : D96[...]) + bc[l]
// stage1 v6: v3 tile (4e2 x 6l) with STRIDED-PAIR l ownership -> every
// b-LDS.64 is two contiguous 64B segments (1 wavefront, conflict-free).

#define B_    16
#define S_    2048
#define H_    768
#define E_    32
#define L_    97
#define CH    96
#define NROWS 2048
#define NENT  512
#define KTOT  49152
#define DPBLK (B_ * E_ * E_ * CH)

typedef unsigned long long ull;

__device__ float g_ent[NENT * H_];
__device__ float g_zh[NENT * H_];
__device__ float g_zt[NENT * H_];
__device__ float g_w96[KTOT];
__device__ float g_C[(size_t)NENT * H_ * CH];      // 151 MB scratch
__device__ float g_C96[NENT * H_];
__device__ float g_Dp[4 * DPBLK];                  // 25 MB partials
__device__ float g_D96[B_ * E_ * E_];

__device__ __forceinline__ ull ffma2(ull a, ull b, ull c) {
    ull d; asm("fma.rn.f32x2 %0, %1, %2, %3;" : "=l"(d) : "l"(a), "l"(b), "l"(c));
    return d;
}
__device__ __forceinline__ ull fsplat(float x) {
    ull d; asm("mov.b64 %0, {%1, %1};" : "=l"(d) : "f"(x));
    return d;
}
__device__ __forceinline__ float lo32(ull v) { return __uint_as_float((unsigned)(v & 0xffffffffull)); }
__device__ __forceinline__ float hi32(ull v) { return __uint_as_float((unsigned)(v >> 32)); }
__device__ __forceinline__ void cp16(uint32_t dst, const void* src) {
    asm volatile("cp.async.cg.shared.global [%0], [%1], 16;" :: "r"(dst), "l"(src));
}

// ---------------------------------------------------------------- kernel 1
__global__ void build_ent_kernel(const float* __restrict__ feats,
                                 const int* __restrict__ pos) {
    int be = blockIdx.x;
    int b  = be >> 5;
    const int* pp = pos + be * 4;
    int p0 = pp[0], p1 = pp[1], p2 = pp[2], p3 = pp[3];
    float w1 = (p1 != p0) ? 1.f : 0.f;
    float w2 = (p2 != p0 && p2 != p1) ? 1.f : 0.f;
    float w3 = (p3 != p0 && p3 != p1 && p3 != p2) ? 1.f : 0.f;
    const float* base = feats + (size_t)b * S_ * H_;
    const float4* r0 = (const float4*)(base + (size_t)p0 * H_);
    const float4* r1 = (const float4*)(base + (size_t)p1 * H_);
    const float4* r2 = (const float4*)(base + (size_t)p2 * H_);
    const float4* r3 = (const float4*)(base + (size_t)p3 * H_);
    int t = threadIdx.x;   // 192 threads * float4 = 768
    float4 v0 = r0[t], v1 = r1[t], v2 = r2[t], v3 = r3[t];
    float4 o;
    o.x = v0.x + w1 * v1.x + w2 * v2.x + w3 * v3.x;
    o.y = v0.y + w1 * v1.y + w2 * v2.y + w3 * v3.y;
    o.z = v0.z + w1 * v1.z + w2 * v2.z + w3 * v3.z;
    o.w = v0.w + w1 * v1.w + w2 * v2.w + w3 * v3.w;
    ((float4*)(g_ent + (size_t)be * H_))[t] = o;
}

// ---------------------------------------------------------------- kernel 2
__global__ void __launch_bounds__(256)
gemm_tanh_kernel(const float* __restrict__ Wh, const float* __restrict__ bh,
                 const float* __restrict__ Wt, const float* __restrict__ bt) {
    const float* W    = blockIdx.z ? Wt : Wh;
    const float* bias = blockIdx.z ? bt : bh;
    float*       Z    = blockIdx.z ? g_zt : g_zh;

    __shared__ float AsT[16 * 68];
    __shared__ float Bd[16 * 256];

    int tid = threadIdx.x;
    int mg  = tid & 15;
    int ng  = tid >> 4;
    int m0  = blockIdx.x * 64;
    int n0  = blockIdx.y * 128;

    ull acc[2][8];
#pragma unroll
    for (int p = 0; p < 2; p++)
#pragma unroll
        for (int c = 0; c < 8; c++) acc[p][c] = 0ull;

    for (int k0 = 0; k0 < H_; k0 += 16) {
        __syncthreads();
#pragma unroll
        for (int e = tid; e < 1024; e += 256) {
            int kk = e & 15, m = e >> 4;
            AsT[kk * 68 + m] = g_ent[(m0 + m) * H_ + k0 + kk];
        }
#pragma unroll
        for (int e = tid; e < 2048; e += 256) {
            int n = e & 127, kk = e >> 7;
            float w = W[(k0 + kk) * H_ + n0 + n];
            ((float2*)Bd)[kk * 128 + n] = make_float2(w, w);
        }
        __syncthreads();
#pragma unroll
        for (int kk = 0; kk < 16; kk++) {
            ulonglong2 av = *(const ulonglong2*)&AsT[kk * 68 + mg * 4];
            const ulonglong2* wp = (const ulonglong2*)&Bd[kk * 256 + ng * 16];
            ulonglong2 w01 = wp[0], w23 = wp[1], w45 = wp[2], w67 = wp[3];
            ull w[8] = {w01.x, w01.y, w23.x, w23.y, w45.x, w45.y, w67.x, w67.y};
#pragma unroll
            for (int c = 0; c < 8; c++) {
                acc[0][c] = ffma2(av.x, w[c], acc[0][c]);
                acc[1][c] = ffma2(av.y, w[c], acc[1][c]);
            }
        }
    }
#pragma unroll
    for (int p = 0; p < 2; p++) {
#pragma unroll
        for (int c = 0; c < 8; c++) {
            int n = n0 + ng * 8 + c;
            float bv = bias[n];
            int m = m0 + mg * 4 + 2 * p;
            Z[m * H_ + n]       = tanhf(lo32(acc[p][c]) + bv);
            Z[(m + 1) * H_ + n] = tanhf(hi32(acc[p][c]) + bv);
        }
    }
}

// ---------------------------------------------------------------- w96 extract
__global__ void w96_extract_kernel(const float* __restrict__ Wc) {
    int k = blockIdx.x * blockDim.x + threadIdx.x;
    if (k < KTOT) g_w96[k] = Wc[(size_t)k * L_ + 96];
}

// ---------------------------------------------------------------- stage 1 v6
// Grid (12 cb, 8 e2-tiles of 64, 64 = 32 i-pairs x 2 l-halves), 256 threads.
// Thread tile 4 e2 x 6 l, l owned as 3 pairs at {il*48 + p*16 + 2*lblk}.
// Per warp-k: a = 1 broadcast wavefront, b = 3 x 1 wavefront (contiguous
// 64B segments, all 32 banks distinct) -> 4 LDS-cyc vs 12 FMA-cyc.
__global__ void __launch_bounds__(256)
stage1_kernel(const float* __restrict__ Wc) {
    __shared__ float As[64 * 68];      // [j][e2], stride 68  (17.4KB)
    __shared__ float Bs[64 * 96];      // [j][il*48 + l]      (24.6KB)

    int tid = threadIdx.x;
    int cb  = blockIdx.x;
    int e0  = blockIdx.y * 64;
    int z   = blockIdx.z;
    int ip  = z >> 1;                  // i-pair 0..31
    int lh  = z & 1;                   // l-half

    for (int e = tid; e < 4096; e += 256) {
        int j = e & 63, m = e >> 6;
        As[j * 68 + m] = g_zt[(e0 + m) * H_ + cb * 64 + j];
    }
    for (int e = tid; e < 6144; e += 256) {
        int row = e / 48, l = e - row * 48;     // row = il*64 + j
        int il = row >> 6, j = row & 63;
        Bs[j * 96 + il * 48 + l] =
            Wc[(size_t)((cb * 64 + ip * 2 + il) * 64 + j) * L_ + lh * 48 + l];
    }
    __syncthreads();

    int mg = tid >> 4;                 // e2 group (4 rows); 2 per warp
    int ng = tid & 15;
    int il = ng >> 3;
    int lb = ng & 7;                   // pair lane: l = il*48 + p*16 + 2*lb
    const float* aptr = As + mg * 4;
    const float* bptr = Bs + il * 48 + 2 * lb;

    ull acc[4][3];
#pragma unroll
    for (int m = 0; m < 4; m++)
#pragma unroll
        for (int p = 0; p < 3; p++) acc[m][p] = 0ull;

#pragma unroll 4
    for (int k = 0; k < 64; k++) {
        float4 a = *(const float4*)(aptr + k * 68);
        ull b0 = *(const ull*)(bptr + k * 96);
        ull b1 = *(const ull*)(bptr + k * 96 + 16);
        ull b2 = *(const ull*)(bptr + k * 96 + 32);
        ull s0 = fsplat(a.x), s1 = fsplat(a.y), s2 = fsplat(a.z), s3 = fsplat(a.w);
        acc[0][0] = ffma2(s0, b0, acc[0][0]);
        acc[0][1] = ffma2(s0, b1, acc[0][1]);
        acc[0][2] = ffma2(s0, b2, acc[0][2]);
        acc[1][0] = ffma2(s1, b0, acc[1][0]);
        acc[1][1] = ffma2(s1, b1, acc[1][1]);
        acc[1][2] = ffma2(s1, b2, acc[1][2]);
        acc[2][0] = ffma2(s2, b0, acc[2][0]);
        acc[2][1] = ffma2(s2, b1, acc[2][1]);
        acc[2][2] = ffma2(s2, b2, acc[2][2]);
        acc[3][0] = ffma2(s3, b0, acc[3][0]);
        acc[3][1] = ffma2(s3, b1, acc[3][1]);
        acc[3][2] = ffma2(s3, b2, acc[3][2]);
    }

    int k1 = cb * 64 + ip * 2 + il;
#pragma unroll
    for (int m = 0; m < 4; m++) {
        float* cptr = g_C + ((size_t)(e0 + mg * 4 + m) * H_ + k1) * CH
                      + lh * 48 + 2 * lb;
        *(ull*)(cptr + 0)  = acc[m][0];
        *(ull*)(cptr + 16) = acc[m][1];
        *(ull*)(cptr + 32) = acc[m][2];
    }
}

// ---------------------------------------------------------------- c96
__global__ void __launch_bounds__(256)
c96_kernel() {
    __shared__ float zts[64 * 68];
    __shared__ float wts[64 * 64];

    int tid = threadIdx.x;
    int cb  = blockIdx.x;
    int e0  = blockIdx.y * 64;

    for (int e = tid; e < 4096; e += 256) {
        int j = e & 63, m = e >> 6;
        zts[j * 68 + m] = g_zt[(e0 + m) * H_ + cb * 64 + j];
    }
    for (int e = tid; e < 1024; e += 256)
        ((float4*)wts)[e] = ((const float4*)(g_w96 + cb * 4096))[e];
    __syncthreads();

    int mg = tid & 15;
    int i0 = (tid >> 4) * 4;

    ull acc[2][4];
#pragma unroll
    for (int p = 0; p < 2; p++)
#pragma unroll
        for (int i = 0; i < 4; i++) acc[p][i] = 0ull;

#pragma unroll 4
    for (int j = 0; j < 64; j++) {
        ulonglong2 a = *(const ulonglong2*)&zts[j * 68 + mg * 4];
#pragma unroll
        for (int i = 0; i < 4; i++) {
            ull w = fsplat(wts[(i0 + i) * 64 + j]);
            acc[0][i] = ffma2(a.x, w, acc[0][i]);
            acc[1][i] = ffma2(a.y, w, acc[1][i]);
        }
    }

#pragma unroll
    for (int p = 0; p < 2; p++) {
        int e2a = e0 + mg * 4 + 2 * p;
#pragma unroll
        for (int i = 0; i < 4; i++) {
            int k1 = cb * 64 + i0 + i;
            g_C96[e2a * H_ + k1]       = lo32(acc[p][i]);
            g_C96[(e2a + 1) * H_ + k1] = hi32(acc[p][i]);
        }
    }
}

// ---------------------------------------------------------------- stage 2
// Dp[z][b,e1,e2,l] = sum_{k in quarter z} zh[b*32+e1,k] * C[b*32+e2,k,l]
// Grid (16 b, 32 e2, 4 z), 256 threads; 3 chunks of 64 k per CTA.
#define S2_AS_F (64 * 36)
#define S2_BS_F (64 * 96)
#define S2_SMEM ((S2_AS_F + 2 * S2_BS_F) * 4)
__global__ void __launch_bounds__(256)
stage2_kernel() {
    extern __shared__ float s2[];
    float* As = s2;                    // [kk][e1], stride 36
    float* Bs = s2 + S2_AS_F;          // [2][kk][96]

    int tid = threadIdx.x;
    int b   = blockIdx.x;
    int e2  = blockIdx.y;
    int z   = blockIdx.z;
    const float* crow = g_C + (size_t)(b * E_ + e2) * H_ * CH + (size_t)(z * 192) * CH;
    const float* zrow = g_zh + (size_t)(b * E_) * H_ + z * 192;
    uint32_t bs_u = (uint32_t)__cvta_generic_to_shared(Bs);

    int mg = tid >> 4;
    int ng = tid & 15;
    int l0 = ng * 6;

    float pa[8];
#pragma unroll
    for (int s = 0; s < 8; s++) {
        int e = tid + s * 256, e1 = e >> 6, kk = e & 63;
        pa[s] = zrow[e1 * H_ + kk];
    }
#pragma unroll
    for (int s = 0; s < 6; s++) {
        int u = tid + s * 256;
        int k = u / 24, c = u - k * 24;
        cp16(bs_u + (unsigned)(k * 96 + c * 4) * 4, crow + (size_t)k * CH + c * 4);
    }
    asm volatile("cp.async.commit_group;");

    ull acc[2][3];
#pragma unroll
    for (int m = 0; m < 2; m++)
#pragma unroll
        for (int p = 0; p < 3; p++) acc[m][p] = 0ull;

    for (int kc = 0; kc < 3; kc++) {
        int buf = kc & 1;
        asm volatile("cp.async.wait_group 0;");
        __syncthreads();
#pragma unroll
        for (int s = 0; s < 8; s++) {
            int e = tid + s * 256, e1 = e >> 6, kk = e & 63;
            As[kk * 36 + e1] = pa[s];
        }
        if (kc < 2) {
            const float* cc = crow + (size_t)(kc + 1) * 64 * CH;
            uint32_t db = bs_u + (unsigned)((buf ^ 1) * S2_BS_F) * 4;
#pragma unroll
            for (int s = 0; s < 6; s++) {
                int u = tid + s * 256;
                int k = u / 24, c = u - k * 24;
                cp16(db + (unsigned)(k * 96 + c * 4) * 4, cc + (size_t)k * CH + c * 4);
            }
            asm volatile("cp.async.commit_group;");
        }
        __syncthreads();
        if (kc < 2) {
            const float* zc = zrow + (kc + 1) * 64;
#pragma unroll
            for (int s = 0; s < 8; s++) {
                int e = tid + s * 256, e1 = e >> 6, kk = e & 63;
                pa[s] = zc[e1 * H_ + kk];
            }
        }

        const float* bb = Bs + buf * S2_BS_F + l0;
#pragma unroll 4
        for (int k = 0; k < 64; k++) {
            ull a = *(const ull*)&As[k * 36 + mg * 2];
            ull s0 = fsplat(lo32(a));
            ull s1 = fsplat(hi32(a));
            ull b0 = *(const ull*)(bb + k * 96);
            ull b1 = *(const ull*)(bb + k * 96 + 2);
            ull b2 = *(const ull*)(bb + k * 96 + 4);
            acc[0][0] = ffma2(s0, b0, acc[0][0]);
            acc[1][0] = ffma2(s1, b0, acc[1][0]);
            acc[0][1] = ffma2(s0, b1, acc[0][1]);
            acc[1][1] = ffma2(s1, b1, acc[1][1]);
            acc[0][2] = ffma2(s0, b2, acc[0][2]);
            acc[1][2] = ffma2(s1, b2, acc[1][2]);
        }
    }

#pragma unroll
    for (int m = 0; m < 2; m++) {
        int e1 = mg * 2 + m;
        float* dptr = g_Dp + (size_t)z * DPBLK +
                      (size_t)((b * E_ + e1) * E_ + e2) * CH + l0;
        *(ull*)(dptr + 0) = acc[m][0];
        *(ull*)(dptr + 2) = acc[m][1];
        *(ull*)(dptr + 4) = acc[m][2];
    }
}

// ---------------------------------------------------------------- d96
__global__ void __launch_bounds__(128)
d96_kernel() {
    __shared__ float c96s[H_];
    int b  = blockIdx.x;
    int e2 = blockIdx.y;
    int tid = threadIdx.x;
    const float* crow = g_C96 + (size_t)(b * E_ + e2) * H_;
    for (int s = tid; s < H_ / 4; s += 128)
        ((float4*)c96s)[s] = ((const float4*)crow)[s];
    __syncthreads();

    int e1 = tid >> 2, q = tid & 3;
    const float* zr = g_zh + (size_t)(b * E_ + e1) * H_;
    float acc = 0.f;
#pragma unroll 8
    for (int k = q; k < H_; k += 4) acc += zr[k] * c96s[k];
    acc += __shfl_down_sync(0xffffffffu, acc, 2, 4);
    acc += __shfl_down_sync(0xffffffffu, acc, 1, 4);
    if (q == 0) g_D96[(b * E_ + e1) * E_ + e2] = acc;
}

// ---------------------------------------------------------------- gather
__global__ void gather_kernel(const int* __restrict__ ht,
                              const float* __restrict__ bc,
                              float* __restrict__ out) {
    int idx = blockIdx.x * 256 + threadIdx.x;
    if (idx >= NROWS * L_) return;
    int n = idx / L_, l = idx - n * L_;
    int b  = n >> 7;
    int e1 = ht[2 * n];
    int e2 = ht[2 * n + 1];
    size_t pe = (size_t)((b * E_ + e1) * E_ + e2);
    float v;
    if (l < CH) {
        v = g_Dp[pe * CH + l] + g_Dp[DPBLK + pe * CH + l] +
            g_Dp[2 * DPBLK + pe * CH + l] + g_Dp[3 * DPBLK + pe * CH + l];
    } else {
        v = g_D96[pe];
    }
    out[idx] = v + bc[l];
}

// ---------------------------------------------------------------- launch
extern "C" void kernel_launch(void* const* d_in, const int* in_sizes, int n_in,
                              void* d_out, int out_size) {
    const float* feats = (const float*)d_in[0];
    const int*   pos   = (const int*)d_in[1];
    const int*   ht    = (const int*)d_in[2];
    const float* Wh    = (const float*)d_in[3];
    const float* bh    = (const float*)d_in[4];
    const float* Wt    = (const float*)d_in[5];
    const float* bt    = (const float*)d_in[6];
    const float* Wc    = (const float*)d_in[7];
    const float* bc    = (const float*)d_in[8];
    float*       out   = (float*)d_out;

    cudaFuncSetAttribute(stage2_kernel,
                         cudaFuncAttributeMaxDynamicSharedMemorySize, S2_SMEM);

    build_ent_kernel<<<NENT, 192>>>(feats, pos);                  // 1

    dim3 g2(NENT / 64, H_ / 128, 2);
    gemm_tanh_kernel<<<g2, 256>>>(Wh, bh, Wt, bt);                // 2

    dim3 g5(12, 8, 64);
    stage1_kernel<<<g5, 256>>>(Wc);                               // 3

    dim3 g6(B_, E_, 4);
    stage2_kernel<<<g6, 256, S2_SMEM>>>();                        // 4 (ncu)

    w96_extract_kernel<<<(KTOT + 255) / 256, 256>>>(Wc);          // 5

    dim3 gc(12, 8);
    c96_kernel<<<gc, 256>>>();                                    // 6

    dim3 gd(B_, E_);
    d96_kernel<<<gd, 128>>>();                                    // 7

    gather_kernel<<<(NROWS * L_ + 255) / 256, 256>>>(ht, bc, out); // 8
}

// round 16
// speedup vs baseline: 1.2121x; 1.0291x over previous
#include <cuda_runtime.h>
#include <cstdint>

// DocREDModel: entity-pool -> tanh-projection -> block-bilinear classifier
// B=16 S=2048 H=768 E=32 M=4 P=128 L=97 BLOCK=64
//
// Factorized pipeline:
//   C[e2, k1, l]  = sum_j zt[e2, cb*64+j] * Wc[k1*64+j, l]       (4.8 GF)
//   C96[e2, k1]   = sum_j zt[e2, cb*64+j] * w96[k1*64+j]
//   Dp[z][b,e1,e2,l] = partial over k-quarter z of zh @ C        (2.4 GF)
//   D96[b,e1,e2]  = zh . C96
//   out[n, l]     = (l<96 ? sum_z Dp[z][...] : D96[...]) + bc[l]
// stage1 v6: strided-pair l ownership (1-wavefront b loads).
// stage2 v4: SAME strided-pair trick -> 4 LDS-cyc / 12 FMA-cyc per warp-k.

#define B_    16
#define S_    2048
#define H_    768
#define E_    32
#define L_    97
#define CH    96
#define NROWS 2048
#define NENT  512
#define KTOT  49152
#define DPBLK (B_ * E_ * E_ * CH)

typedef unsigned long long ull;

__device__ float g_ent[NENT * H_];
__device__ float g_zh[NENT * H_];
__device__ float g_zt[NENT * H_];
__device__ float g_w96[KTOT];
__device__ float g_C[(size_t)NENT * H_ * CH];      // 151 MB scratch
__device__ float g_C96[NENT * H_];
__device__ float g_Dp[4 * DPBLK];                  // 25 MB partials
__device__ float g_D96[B_ * E_ * E_];

__device__ __forceinline__ ull ffma2(ull a, ull b, ull c) {
    ull d; asm("fma.rn.f32x2 %0, %1, %2, %3;" : "=l"(d) : "l"(a), "l"(b), "l"(c));
    return d;
}
__device__ __forceinline__ ull fsplat(float x) {
    ull d; asm("mov.b64 %0, {%1, %1};" : "=l"(d) : "f"(x));
    return d;
}
__device__ __forceinline__ float lo32(ull v) { return __uint_as_float((unsigned)(v & 0xffffffffull)); }
__device__ __forceinline__ float hi32(ull v) { return __uint_as_float((unsigned)(v >> 32)); }
__device__ __forceinline__ void cp16(uint32_t dst, const void* src) {
    asm volatile("cp.async.cg.shared.global [%0], [%1], 16;" :: "r"(dst), "l"(src));
}

// ---------------------------------------------------------------- kernel 1
__global__ void build_ent_kernel(const float* __restrict__ feats,
                                 const int* __restrict__ pos) {
    int be = blockIdx.x;
    int b  = be >> 5;
    const int* pp = pos + be * 4;
    int p0 = pp[0], p1 = pp[1], p2 = pp[2], p3 = pp[3];
    float w1 = (p1 != p0) ? 1.f : 0.f;
    float w2 = (p2 != p0 && p2 != p1) ? 1.f : 0.f;
    float w3 = (p3 != p0 && p3 != p1 && p3 != p2) ? 1.f : 0.f;
    const float* base = feats + (size_t)b * S_ * H_;
    const float4* r0 = (const float4*)(base + (size_t)p0 * H_);
    const float4* r1 = (const float4*)(base + (size_t)p1 * H_);
    const float4* r2 = (const float4*)(base + (size_t)p2 * H_);
    const float4* r3 = (const float4*)(base + (size_t)p3 * H_);
    int t = threadIdx.x;   // 192 threads * float4 = 768
    float4 v0 = r0[t], v1 = r1[t], v2 = r2[t], v3 = r3[t];
    float4 o;
    o.x = v0.x + w1 * v1.x + w2 * v2.x + w3 * v3.x;
    o.y = v0.y + w1 * v1.y + w2 * v2.y + w3 * v3.y;
    o.z = v0.z + w1 * v1.z + w2 * v2.z + w3 * v3.z;
    o.w = v0.w + w1 * v1.w + w2 * v2.w + w3 * v3.w;
    ((float4*)(g_ent + (size_t)be * H_))[t] = o;
}

// ---------------------------------------------------------------- kernel 2
__global__ void __launch_bounds__(256)
gemm_tanh_kernel(const float* __restrict__ Wh, const float* __restrict__ bh,
                 const float* __restrict__ Wt, const float* __restrict__ bt) {
    const float* W    = blockIdx.z ? Wt : Wh;
    const float* bias = blockIdx.z ? bt : bh;
    float*       Z    = blockIdx.z ? g_zt : g_zh;

    __shared__ float AsT[16 * 68];
    __shared__ float Bd[16 * 256];

    int tid = threadIdx.x;
    int mg  = tid & 15;
    int ng  = tid >> 4;
    int m0  = blockIdx.x * 64;
    int n0  = blockIdx.y * 128;

    ull acc[2][8];
#pragma unroll
    for (int p = 0; p < 2; p++)
#pragma unroll
        for (int c = 0; c < 8; c++) acc[p][c] = 0ull;

    for (int k0 = 0; k0 < H_; k0 += 16) {
        __syncthreads();
#pragma unroll
        for (int e = tid; e < 1024; e += 256) {
            int kk = e & 15, m = e >> 4;
            AsT[kk * 68 + m] = g_ent[(m0 + m) * H_ + k0 + kk];
        }
#pragma unroll
        for (int e = tid; e < 2048; e += 256) {
            int n = e & 127, kk = e >> 7;
            float w = W[(k0 + kk) * H_ + n0 + n];
            ((float2*)Bd)[kk * 128 + n] = make_float2(w, w);
        }
        __syncthreads();
#pragma unroll
        for (int kk = 0; kk < 16; kk++) {
            ulonglong2 av = *(const ulonglong2*)&AsT[kk * 68 + mg * 4];
            const ulonglong2* wp = (const ulonglong2*)&Bd[kk * 256 + ng * 16];
            ulonglong2 w01 = wp[0], w23 = wp[1], w45 = wp[2], w67 = wp[3];
            ull w[8] = {w01.x, w01.y, w23.x, w23.y, w45.x, w45.y, w67.x, w67.y};
#pragma unroll
            for (int c = 0; c < 8; c++) {
                acc[0][c] = ffma2(av.x, w[c], acc[0][c]);
                acc[1][c] = ffma2(av.y, w[c], acc[1][c]);
            }
        }
    }
#pragma unroll
    for (int p = 0; p < 2; p++) {
#pragma unroll
        for (int c = 0; c < 8; c++) {
            int n = n0 + ng * 8 + c;
            float bv = bias[n];
            int m = m0 + mg * 4 + 2 * p;
            Z[m * H_ + n]       = tanhf(lo32(acc[p][c]) + bv);
            Z[(m + 1) * H_ + n] = tanhf(hi32(acc[p][c]) + bv);
        }
    }
}

// ---------------------------------------------------------------- w96 extract
__global__ void w96_extract_kernel(const float* __restrict__ Wc) {
    int k = blockIdx.x * blockDim.x + threadIdx.x;
    if (k < KTOT) g_w96[k] = Wc[(size_t)k * L_ + 96];
}

// ---------------------------------------------------------------- stage 1 v6
// Grid (12 cb, 8 e2-tiles of 64, 64 = 32 i-pairs x 2 l-halves), 256 threads.
// Thread tile 4 e2 x 6 l, l owned as 3 pairs at {il*48 + p*16 + 2*lb}.
__global__ void __launch_bounds__(256)
stage1_kernel(const float* __restrict__ Wc) {
    __shared__ float As[64 * 68];      // [j][e2], stride 68
    __shared__ float Bs[64 * 96];      // [j][il*48 + l]

    int tid = threadIdx.x;
    int cb  = blockIdx.x;
    int e0  = blockIdx.y * 64;
    int z   = blockIdx.z;
    int ip  = z >> 1;
    int lh  = z & 1;

    for (int e = tid; e < 4096; e += 256) {
        int j = e & 63, m = e >> 6;
        As[j * 68 + m] = g_zt[(e0 + m) * H_ + cb * 64 + j];
    }
    for (int e = tid; e < 6144; e += 256) {
        int row = e / 48, l = e - row * 48;
        int il = row >> 6, j = row & 63;
        Bs[j * 96 + il * 48 + l] =
            Wc[(size_t)((cb * 64 + ip * 2 + il) * 64 + j) * L_ + lh * 48 + l];
    }
    __syncthreads();

    int mg = tid >> 4;
    int ng = tid & 15;
    int il = ng >> 3;
    int lb = ng & 7;
    const float* aptr = As + mg * 4;
    const float* bptr = Bs + il * 48 + 2 * lb;

    ull acc[4][3];
#pragma unroll
    for (int m = 0; m < 4; m++)
#pragma unroll
        for (int p = 0; p < 3; p++) acc[m][p] = 0ull;

#pragma unroll 4
    for (int k = 0; k < 64; k++) {
        float4 a = *(const float4*)(aptr + k * 68);
        ull b0 = *(const ull*)(bptr + k * 96);
        ull b1 = *(const ull*)(bptr + k * 96 + 16);
        ull b2 = *(const ull*)(bptr + k * 96 + 32);
        ull s0 = fsplat(a.x), s1 = fsplat(a.y), s2 = fsplat(a.z), s3 = fsplat(a.w);
        acc[0][0] = ffma2(s0, b0, acc[0][0]);
        acc[0][1] = ffma2(s0, b1, acc[0][1]);
        acc[0][2] = ffma2(s0, b2, acc[0][2]);
        acc[1][0] = ffma2(s1, b0, acc[1][0]);
        acc[1][1] = ffma2(s1, b1, acc[1][1]);
        acc[1][2] = ffma2(s1, b2, acc[1][2]);
        acc[2][0] = ffma2(s2, b0, acc[2][0]);
        acc[2][1] = ffma2(s2, b1, acc[2][1]);
        acc[2][2] = ffma2(s2, b2, acc[2][2]);
        acc[3][0] = ffma2(s3, b0, acc[3][0]);
        acc[3][1] = ffma2(s3, b1, acc[3][1]);
        acc[3][2] = ffma2(s3, b2, acc[3][2]);
    }

    int k1 = cb * 64 + ip * 2 + il;
#pragma unroll
    for (int m = 0; m < 4; m++) {
        float* cptr = g_C + ((size_t)(e0 + mg * 4 + m) * H_ + k1) * CH
                      + lh * 48 + 2 * lb;
        *(ull*)(cptr + 0)  = acc[m][0];
        *(ull*)(cptr + 16) = acc[m][1];
        *(ull*)(cptr + 32) = acc[m][2];
    }
}

// ---------------------------------------------------------------- c96
__global__ void __launch_bounds__(256)
c96_kernel() {
    __shared__ float zts[64 * 68];
    __shared__ float wts[64 * 64];

    int tid = threadIdx.x;
    int cb  = blockIdx.x;
    int e0  = blockIdx.y * 64;

    for (int e = tid; e < 4096; e += 256) {
        int j = e & 63, m = e >> 6;
        zts[j * 68 + m] = g_zt[(e0 + m) * H_ + cb * 64 + j];
    }
    for (int e = tid; e < 1024; e += 256)
        ((float4*)wts)[e] = ((const float4*)(g_w96 + cb * 4096))[e];
    __syncthreads();

    int mg = tid & 15;
    int i0 = (tid >> 4) * 4;

    ull acc[2][4];
#pragma unroll
    for (int p = 0; p < 2; p++)
#pragma unroll
        for (int i = 0; i < 4; i++) acc[p][i] = 0ull;

#pragma unroll 4
    for (int j = 0; j < 64; j++) {
        ulonglong2 a = *(const ulonglong2*)&zts[j * 68 + mg * 4];
#pragma unroll
        for (int i = 0; i < 4; i++) {
            ull w = fsplat(wts[(i0 + i) * 64 + j]);
            acc[0][i] = ffma2(a.x, w, acc[0][i]);
            acc[1][i] = ffma2(a.y, w, acc[1][i]);
        }
    }

#pragma unroll
    for (int p = 0; p < 2; p++) {
        int e2a = e0 + mg * 4 + 2 * p;
#pragma unroll
        for (int i = 0; i < 4; i++) {
            int k1 = cb * 64 + i0 + i;
            g_C96[e2a * H_ + k1]       = lo32(acc[p][i]);
            g_C96[(e2a + 1) * H_ + k1] = hi32(acc[p][i]);
        }
    }
}

// ---------------------------------------------------------------- stage 2 v4
// Dp[z][b,e1,e2,l] = sum_{k in quarter z} zh[b*32+e1,k] * C[b*32+e2,k,l]
// Grid (16 b, 32 e2, 4 z), 256 threads; 3 chunks of 64 k per CTA.
// Thread tile 2 e1 x 6 l with STRIDED-PAIR l ownership {2ng, 2ng+32, 2ng+64}:
// each b-LDS.64 is one contiguous 128B warp segment -> 1 wavefront.
#define S2_AS_F (64 * 36)
#define S2_BS_F (64 * 96)
#define S2_SMEM ((S2_AS_F + 2 * S2_BS_F) * 4)
__global__ void __launch_bounds__(256)
stage2_kernel() {
    extern __shared__ float s2[];
    float* As = s2;                    // [kk][e1], stride 36
    float* Bs = s2 + S2_AS_F;          // [2][kk][96]

    int tid = threadIdx.x;
    int b   = blockIdx.x;
    int e2  = blockIdx.y;
    int z   = blockIdx.z;
    const float* crow = g_C + (size_t)(b * E_ + e2) * H_ * CH + (size_t)(z * 192) * CH;
    const float* zrow = g_zh + (size_t)(b * E_) * H_ + z * 192;
    uint32_t bs_u = (uint32_t)__cvta_generic_to_shared(Bs);

    int mg = tid >> 4;                 // 16 groups -> 2 e1
    int ng = tid & 15;                 // l pairs at 2ng + 32p
    int l0 = 2 * ng;

    float pa[8];
#pragma unroll
    for (int s = 0; s < 8; s++) {
        int e = tid + s * 256, e1 = e >> 6, kk = e & 63;
        pa[s] = zrow[e1 * H_ + kk];
    }
#pragma unroll
    for (int s = 0; s < 6; s++) {
        int u = tid + s * 256;
        int k = u / 24, c = u - k * 24;
        cp16(bs_u + (unsigned)(k * 96 + c * 4) * 4, crow + (size_t)k * CH + c * 4);
    }
    asm volatile("cp.async.commit_group;");

    ull acc[2][3];
#pragma unroll
    for (int m = 0; m < 2; m++)
#pragma unroll
        for (int p = 0; p < 3; p++) acc[m][p] = 0ull;

    for (int kc = 0; kc < 3; kc++) {
        int buf = kc & 1;
        asm volatile("cp.async.wait_group 0;");
        __syncthreads();               // B(kc) visible; prior reads done
#pragma unroll
        for (int s = 0; s < 8; s++) {
            int e = tid + s * 256, e1 = e >> 6, kk = e & 63;
            As[kk * 36 + e1] = pa[s];
        }
        if (kc < 2) {
            const float* cc = crow + (size_t)(kc + 1) * 64 * CH;
            uint32_t db = bs_u + (unsigned)((buf ^ 1) * S2_BS_F) * 4;
#pragma unroll
            for (int s = 0; s < 6; s++) {
                int u = tid + s * 256;
                int k = u / 24, c = u - k * 24;
                cp16(db + (unsigned)(k * 96 + c * 4) * 4, cc + (size_t)k * CH + c * 4);
            }
            asm volatile("cp.async.commit_group;");
        }
        __syncthreads();               // As ready
        if (kc < 2) {
            const float* zc = zrow + (kc + 1) * 64;
#pragma unroll
            for (int s = 0; s < 8; s++) {
                int e = tid + s * 256, e1 = e >> 6, kk = e & 63;
                pa[s] = zc[e1 * H_ + kk];
            }
        }

        const float* bb = Bs + buf * S2_BS_F + l0;
#pragma unroll 4
        for (int k = 0; k < 64; k++) {
            ull a = *(const ull*)&As[k * 36 + mg * 2];
            ull s0 = fsplat(lo32(a));
            ull s1 = fsplat(hi32(a));
            ull b0 = *(const ull*)(bb + k * 96);
            ull b1 = *(const ull*)(bb + k * 96 + 32);
            ull b2 = *(const ull*)(bb + k * 96 + 64);
            acc[0][0] = ffma2(s0, b0, acc[0][0]);
            acc[1][0] = ffma2(s1, b0, acc[1][0]);
            acc[0][1] = ffma2(s0, b1, acc[0][1]);
            acc[1][1] = ffma2(s1, b1, acc[1][1]);
            acc[0][2] = ffma2(s0, b2, acc[0][2]);
            acc[1][2] = ffma2(s1, b2, acc[1][2]);
        }
    }

#pragma unroll
    for (int m = 0; m < 2; m++) {
        int e1 = mg * 2 + m;
        float* dptr = g_Dp + (size_t)z * DPBLK +
                      (size_t)((b * E_ + e1) * E_ + e2) * CH + l0;
        *(ull*)(dptr + 0)  = acc[m][0];
        *(ull*)(dptr + 32) = acc[m][1];
        *(ull*)(dptr + 64) = acc[m][2];
    }
}

// ---------------------------------------------------------------- d96
__global__ void __launch_bounds__(128)
d96_kernel() {
    __shared__ float c96s[H_];
    int b  = blockIdx.x;
    int e2 = blockIdx.y;
    int tid = threadIdx.x;
    const float* crow = g_C96 + (size_t)(b * E_ + e2) * H_;
    for (int s = tid; s < H_ / 4; s += 128)
        ((float4*)c96s)[s] = ((const float4*)crow)[s];
    __syncthreads();

    int e1 = tid >> 2, q = tid & 3;
    const float* zr = g_zh + (size_t)(b * E_ + e1) * H_;
    float acc = 0.f;
#pragma unroll 8
    for (int k = q; k < H_; k += 4) acc += zr[k] * c96s[k];
    acc += __shfl_down_sync(0xffffffffu, acc, 2, 4);
    acc += __shfl_down_sync(0xffffffffu, acc, 1, 4);
    if (q == 0) g_D96[(b * E_ + e1) * E_ + e2] = acc;
}

// ---------------------------------------------------------------- gather
__global__ void gather_kernel(const int* __restrict__ ht,
                              const float* __restrict__ bc,
                              float* __restrict__ out) {
    int idx = blockIdx.x * 256 + threadIdx.x;
    if (idx >= NROWS * L_) return;
    int n = idx / L_, l = idx - n * L_;
    int b  = n >> 7;
    int e1 = ht[2 * n];
    int e2 = ht[2 * n + 1];
    size_t pe = (size_t)((b * E_ + e1) * E_ + e2);
    float v;
    if (l < CH) {
        v = g_Dp[pe * CH + l] + g_Dp[DPBLK + pe * CH + l] +
            g_Dp[2 * DPBLK + pe * CH + l] + g_Dp[3 * DPBLK + pe * CH + l];
    } else {
        v = g_D96[pe];
    }
    out[idx] = v + bc[l];
}

// ---------------------------------------------------------------- launch
extern "C" void kernel_launch(void* const* d_in, const int* in_sizes, int n_in,
                              void* d_out, int out_size) {
    const float* feats = (const float*)d_in[0];
    const int*   pos   = (const int*)d_in[1];
    const int*   ht    = (const int*)d_in[2];
    const float* Wh    = (const float*)d_in[3];
    const float* bh    = (const float*)d_in[4];
    const float* Wt    = (const float*)d_in[5];
    const float* bt    = (const float*)d_in[6];
    const float* Wc    = (const float*)d_in[7];
    const float* bc    = (const float*)d_in[8];
    float*       out   = (float*)d_out;

    cudaFuncSetAttribute(stage2_kernel,
                         cudaFuncAttributeMaxDynamicSharedMemorySize, S2_SMEM);

    build_ent_kernel<<<NENT, 192>>>(feats, pos);                  // 1

    dim3 g2(NENT / 64, H_ / 128, 2);
    gemm_tanh_kernel<<<g2, 256>>>(Wh, bh, Wt, bt);                // 2

    w96_extract_kernel<<<(KTOT + 255) / 256, 256>>>(Wc);          // 3

    dim3 g5(12, 8, 64);
    stage1_kernel<<<g5, 256>>>(Wc);                               // 4 (ncu)

    dim3 gc(12, 8);
    c96_kernel<<<gc, 256>>>();                                    // 5

    dim3 g6(B_, E_, 4);
    stage2_kernel<<<g6, 256, S2_SMEM>>>();                        // 6

    dim3 gd(B_, E_);
    d96_kernel<<<gd, 128>>>();                                    // 7

    gather_kernel<<<(NROWS * L_ + 255) / 256, 256>>>(ht, bc, out); // 8
}